// round 13
// baseline (speedup 1.0000x reference)
#include <cuda_runtime.h>
#include <math.h>

#define RBM_B 2048
#define RBM_V 4096
#define RBM_H 1024

// Scratch (device globals: allocation-free rule)
static __device__ float g_WT[(size_t)RBM_H * RBM_V];   // 16 MB  W transposed [H,V]
static __device__ float g_h [(size_t)RBM_B * RBM_H];   //  8 MB  current h
static __device__ float g_v [(size_t)RBM_B * RBM_V];   // 32 MB  current v
static __device__ float g_pos[RBM_B * 16];             // pos partials (16 n-tiles, BN=64)
static __device__ float g_neg[RBM_B * 64];             // neg partials (64 n-tiles, BN=64)

typedef unsigned long long u64;

// packed f32x2 FMA (full-rate fp32 on sm_103a; per-lane rounding == scalar FFMA)
__device__ __forceinline__ void ffma2(u64& d, u64 a, u64 b) {
    asm("fma.rn.f32x2 %0, %1, %2, %0;" : "+l"(d) : "l"(a), "l"(b));
}
__device__ __forceinline__ u64 dup32(float v) {
    unsigned u = __float_as_uint(v);
    return (u64)u | ((u64)u << 32);
}
// register dup via PRMT (alu pipe; keeps the fma pipe clean)
__device__ __forceinline__ u64 dupr(float x) {
    unsigned lo = __float_as_uint(x), hi;
    asm("prmt.b32 %0, %1, %1, 0x3210;" : "=r"(hi) : "r"(lo));
    u64 d;
    asm("mov.b64 %0, {%1, %2};" : "=l"(d) : "r"(lo), "r"(hi));
    return d;
}

// ---------------- transpose W[V,H] -> WT[H,V] ----------------
__global__ void k_transpose(const float* __restrict__ W, float* __restrict__ WT) {
    __shared__ float t[32][33];
    int h0 = blockIdx.x * 32, v0 = blockIdx.y * 32;
#pragma unroll
    for (int i = 0; i < 4; ++i)
        t[threadIdx.y + 8*i][threadIdx.x] =
            W[(size_t)(v0 + threadIdx.y + 8*i) * RBM_H + h0 + threadIdx.x];
    __syncthreads();
#pragma unroll
    for (int i = 0; i < 4; ++i)
        WT[(size_t)(h0 + threadIdx.y + 8*i) * RBM_V + v0 + threadIdx.x] =
            t[threadIdx.x][threadIdx.y + 8*i];
}

// ---------------- fused GEMM + bias + sigmoid-Bernoulli sample (+score) ----------------
// C[M,N] = A[M,K] * Bm[K,N]; A binary {0,1}.
// CRITICAL: one accumulator per output element, strict ascending-k fma.rn.f32x2 chain
// (bit-identical logits to all passing rounds). SIMD pairs along n.
// BM=128, BN=64, BK=16, 128 threads, thread tile 8m x 8n.
// A stored PLAIN in smem (half the fill traffic + half the in-loop A wavefronts);
// the f32x2 A-duplicates are built per-kk in registers via PRMT (alu pipe).
// PIPE=1 (H-out, grid 256): next-kk operand preload, __launch_bounds__(128,2).
// PIPE=0 (V-out, grid 1024, 3 CTA/SM): plain body, bounds(128,3).
template<int SCORE, int PIPE>
__global__ __launch_bounds__(128, (PIPE ? 2 : 3))
void k_gemm_sample(const float* __restrict__ A, const float* __restrict__ Bm,
                   const float* __restrict__ bias, const float* __restrict__ U,
                   float* __restrict__ Out, float* __restrict__ Score,
                   int K, int N)
{
    constexpr int BM = 128, BN = 64, BK = 16;
    __shared__ __align__(16) float As[2][BK][BM];      // plain A: 16 KB
    __shared__ __align__(16) float Bs[2][BK][BN];      // plain B: 8 KB

    const int tid = threadIdx.x;
    const int tx = tid & 7, ty = tid >> 3;
    const int m0 = blockIdx.y * BM, n0 = blockIdx.x * BN;

    // A loader: thread tid owns row m0+tid, loads 16 consecutive k per tile.
    const float* Aload = A + (size_t)(m0 + tid) * K;
    // B loader: 16 rows x 64 floats, 8 per thread.
    const int brow = tid >> 3, bcol = (tid & 7) * 8;
    const float* Bload = Bm + (size_t)brow * N + n0 + bcol;

    // acc[m 0..7][j 0..3]: u64 = fp32 pair, cols ((j>>1)*32 + tx*4 + 2*(j&1), +1)
    u64 acc[8][4];
#pragma unroll
    for (int m = 0; m < 8; ++m)
#pragma unroll
        for (int j = 0; j < 4; ++j) acc[m][j] = 0ull;

    float4 pa[4], pb[2];

    // ---- prologue: tile 0 ----
#pragma unroll
    for (int q = 0; q < 4; ++q) pa[q] = *(const float4*)(Aload + q * 4);
#pragma unroll
    for (int q = 0; q < 2; ++q) pb[q] = *(const float4*)(Bload + q * 4);
#pragma unroll
    for (int c = 0; c < 16; ++c)
        As[0][c][tid] = ((const float*)&pa[0])[c];
#pragma unroll
    for (int q = 0; q < 2; ++q)
        *(float4*)&Bs[0][brow][bcol + q * 4] = pb[q];
    __syncthreads();

    const int nk = K / BK;
    int buf = 0;
    for (int t = 0; t < nk; ++t) {
        if (t + 1 < nk) {
            const float* Ap = Aload + (t + 1) * BK;
            const float* Bp = Bload + (size_t)(t + 1) * BK * N;
#pragma unroll
            for (int q = 0; q < 4; ++q) pa[q] = *(const float4*)(Ap + q * 4);
#pragma unroll
            for (int q = 0; q < 2; ++q) pb[q] = *(const float4*)(Bp + q * 4);
        }
        // strict ascending-k serial accumulation (32 independent FFMA2 chains)
        if (PIPE) {
            // software pipeline the smem reads one kk ahead
            float4 ar[2][2]; u64 br[2][4];
            ar[0][0] = *(const float4*)&As[buf][0][ty * 8];
            ar[0][1] = *(const float4*)&As[buf][0][ty * 8 + 4];
#pragma unroll
            for (int q = 0; q < 2; ++q) {
                ulonglong2 b2 = *(const ulonglong2*)&Bs[buf][0][q * 32 + tx * 4];
                br[0][q * 2] = b2.x; br[0][q * 2 + 1] = b2.y;
            }
#pragma unroll
            for (int kk = 0; kk < BK; ++kk) {
                const int cs = kk & 1;
                if (kk + 1 < BK) {
                    ar[cs ^ 1][0] = *(const float4*)&As[buf][kk + 1][ty * 8];
                    ar[cs ^ 1][1] = *(const float4*)&As[buf][kk + 1][ty * 8 + 4];
#pragma unroll
                    for (int q = 0; q < 2; ++q) {
                        ulonglong2 b2 = *(const ulonglong2*)&Bs[buf][kk + 1][q * 32 + tx * 4];
                        br[cs ^ 1][q * 2] = b2.x; br[cs ^ 1][q * 2 + 1] = b2.y;
                    }
                }
                u64 ap[8];
#pragma unroll
                for (int m = 0; m < 8; ++m)
                    ap[m] = dupr(((const float*)&ar[cs][0])[m]);
#pragma unroll
                for (int m = 0; m < 8; ++m)
#pragma unroll
                    for (int j = 0; j < 4; ++j)
                        ffma2(acc[m][j], ap[m], br[cs][j]);
            }
        } else {
#pragma unroll
            for (int kk = 0; kk < BK; ++kk) {
                float4 a0 = *(const float4*)&As[buf][kk][ty * 8];
                float4 a1 = *(const float4*)&As[buf][kk][ty * 8 + 4];
                u64 ap[8];
#pragma unroll
                for (int m = 0; m < 4; ++m) ap[m]     = dupr(((const float*)&a0)[m]);
#pragma unroll
                for (int m = 0; m < 4; ++m) ap[m + 4] = dupr(((const float*)&a1)[m]);
                u64 bp[4];
#pragma unroll
                for (int q = 0; q < 2; ++q) {
                    ulonglong2 b2 = *(const ulonglong2*)&Bs[buf][kk][q * 32 + tx * 4];
                    bp[q * 2] = b2.x; bp[q * 2 + 1] = b2.y;
                }
#pragma unroll
                for (int m = 0; m < 8; ++m)
#pragma unroll
                    for (int j = 0; j < 4; ++j)
                        ffma2(acc[m][j], ap[m], bp[j]);
            }
        }
        if (t + 1 < nk) {
            int nb = buf ^ 1;
#pragma unroll
            for (int c = 0; c < 16; ++c)
                As[nb][c][tid] = ((const float*)&pa[0])[c];
#pragma unroll
            for (int q = 0; q < 2; ++q)
                *(float4*)&Bs[nb][brow][bcol + q * 4] = pb[q];
        }
        __syncthreads();
        buf ^= 1;
    }

    // ---- epilogue: bias + sigmoid + Bernoulli + optional per-row score partial ----
    float biasv[8];
#pragma unroll
    for (int q = 0; q < 2; ++q)
        *(float4*)&biasv[q * 4] = *(const float4*)(bias + n0 + q * 32 + tx * 4);
#pragma unroll
    for (int m = 0; m < 8; ++m) {
        int gm = m0 + ty * 8 + m;
        float sp = 0.f;
#pragma unroll
        for (int q = 0; q < 2; ++q) {
            int gn = n0 + q * 32 + tx * 4;
            float4 u4 = *(const float4*)(U + (size_t)gm * N + gn);
            float2 e0 = *(float2*)&acc[m][q * 2];
            float2 e1 = *(float2*)&acc[m][q * 2 + 1];
            float l[4] = { e0.x + biasv[q*4],   e0.y + biasv[q*4+1],
                           e1.x + biasv[q*4+2], e1.y + biasv[q*4+3] };
            float s[4];
#pragma unroll
            for (int j = 0; j < 4; ++j) {
                float pr = 1.0f / (1.0f + expf(-l[j]));   // libdevice expf + IEEE div
                s[j] = (pr > ((const float*)&u4)[j]) ? 1.0f : 0.0f;
            }
            *(float4*)(Out + (size_t)gm * N + gn) = make_float4(s[0], s[1], s[2], s[3]);
            if (SCORE) sp += s[0]*l[0] + s[1]*l[1] + s[2]*l[2] + s[3]*l[3];
        }
        if (SCORE) {
            sp += __shfl_xor_sync(0xffffffffu, sp, 1);
            sp += __shfl_xor_sync(0xffffffffu, sp, 2);
            sp += __shfl_xor_sync(0xffffffffu, sp, 4);
            if (tx == 0) Score[(size_t)gm * gridDim.x + blockIdx.x] = sp;
        }
    }
}

// ---------------- finalize: out[b] = (v.b_v + pos) - (neg + h2.b_h) ----------------
__global__ void k_finalize(const float* __restrict__ visible, const float* __restrict__ b_v,
                           const float* __restrict__ b_h, float* __restrict__ out)
{
    int b = blockIdx.x, tid = threadIdx.x;
    float acc = 0.f;
    const float* vr = visible + (size_t)b * RBM_V;
    for (int i = tid; i < RBM_V; i += 256) acc += vr[i] * b_v[i];
    const float* hr = g_h + (size_t)b * RBM_H;            // g_h holds h2 here
    for (int i = tid; i < RBM_H; i += 256) acc -= hr[i] * b_h[i];
    if (tid < 16) acc += g_pos[b * 16 + tid];             // 16 n-tiles (N=1024, BN=64)
    if (tid < 64) acc -= g_neg[b * 64 + tid];             // 64 n-tiles (N=4096, BN=64)
    __shared__ float red[256];
    red[tid] = acc;
    __syncthreads();
    for (int o = 128; o; o >>= 1) { if (tid < o) red[tid] += red[tid + o]; __syncthreads(); }
    if (tid == 0) out[b] = red[0];
}

// ---------------- launch ----------------
extern "C" void kernel_launch(void* const* d_in, const int* in_sizes, int n_in,
                              void* d_out, int out_size)
{
    const float* visible = (const float*)d_in[0];
    const float* b_v     = (const float*)d_in[1];
    const float* b_h     = (const float*)d_in[2];
    const float* W       = (const float*)d_in[3];
    const float* u_h0    = (const float*)d_in[4];
    const float* u_v     = (const float*)d_in[5];
    const float* u_h     = (const float*)d_in[6];
    float* out = (float*)d_out;

    float *WT, *hb, *vb, *pos, *neg;
    cudaGetSymbolAddress((void**)&WT,  g_WT);
    cudaGetSymbolAddress((void**)&hb,  g_h);
    cudaGetSymbolAddress((void**)&vb,  g_v);
    cudaGetSymbolAddress((void**)&pos, g_pos);
    cudaGetSymbolAddress((void**)&neg, g_neg);

    k_transpose<<<dim3(RBM_H / 32, RBM_V / 32), dim3(32, 8)>>>(W, WT);

    dim3 blk(128);
    dim3 gH(RBM_H / 64, RBM_B / 128);   // (16, 16) = 256 CTAs  (PIPE=1)
    dim3 gV(RBM_V / 64, RBM_B / 128);   // (64, 16) = 1024 CTAs (PIPE=0)

    const size_t BV = (size_t)RBM_B * RBM_V;
    const size_t BH = (size_t)RBM_B * RBM_H;

    // positive phase: h0 | data, fused pos-score
    k_gemm_sample<1,1><<<gH, blk>>>(visible, W,  b_h, u_h0,        hb, pos,    RBM_V, RBM_H);
    // Gibbs chain: v,h,v,h,v
    k_gemm_sample<0,0><<<gV, blk>>>(hb,      WT, b_v, u_v + 0*BV,  vb, nullptr, RBM_H, RBM_V);
    k_gemm_sample<0,1><<<gH, blk>>>(vb,      W,  b_h, u_h + 0*BH,  hb, nullptr, RBM_V, RBM_H);
    k_gemm_sample<0,0><<<gV, blk>>>(hb,      WT, b_v, u_v + 1*BV,  vb, nullptr, RBM_H, RBM_V);
    k_gemm_sample<0,1><<<gH, blk>>>(vb,      W,  b_h, u_h + 1*BH,  hb, nullptr, RBM_V, RBM_H);
    // last v-step: fused neg-score
    k_gemm_sample<2,0><<<gV, blk>>>(hb,      WT, b_v, u_v + 2*BV,  vb, neg,     RBM_H, RBM_V);

    k_finalize<<<RBM_B, 256>>>(visible, b_v, b_h, out);
}

// round 14
// speedup vs baseline: 1.0445x; 1.0445x over previous
#include <cuda_runtime.h>
#include <math.h>

#define RBM_B 2048
#define RBM_V 4096
#define RBM_H 1024

// Scratch (device globals: allocation-free rule)
static __device__ float g_WT[(size_t)RBM_H * RBM_V];   // 16 MB  W transposed [H,V]
static __device__ float g_h [(size_t)RBM_B * RBM_H];   //  8 MB  current h
static __device__ float g_v [(size_t)RBM_B * RBM_V];   // 32 MB  current v
static __device__ float g_pos[RBM_B * 16];             // pos partials (16 n-tiles, BN=64)
static __device__ float g_neg[RBM_B * 64];             // neg partials (64 n-tiles, BN=64)

typedef unsigned long long u64;

// packed f32x2 FMA (full-rate fp32 on sm_103a; per-lane rounding == scalar FFMA)
__device__ __forceinline__ void ffma2(u64& d, u64 a, u64 b) {
    asm("fma.rn.f32x2 %0, %1, %2, %0;" : "+l"(d) : "l"(a), "l"(b));
}
__device__ __forceinline__ u64 dup32(float v) {
    unsigned u = __float_as_uint(v);
    return (u64)u | ((u64)u << 32);
}

// ---------------- transpose W[V,H] -> WT[H,V] ----------------
__global__ void k_transpose(const float* __restrict__ W, float* __restrict__ WT) {
    __shared__ float t[32][33];
    int h0 = blockIdx.x * 32, v0 = blockIdx.y * 32;
#pragma unroll
    for (int i = 0; i < 4; ++i)
        t[threadIdx.y + 8*i][threadIdx.x] =
            W[(size_t)(v0 + threadIdx.y + 8*i) * RBM_H + h0 + threadIdx.x];
    __syncthreads();
#pragma unroll
    for (int i = 0; i < 4; ++i)
        WT[(size_t)(h0 + threadIdx.y + 8*i) * RBM_V + v0 + threadIdx.x] =
            t[threadIdx.x][threadIdx.y + 8*i];
}

// ======================= H-output GEMM: BK=32, dynamic smem, PIPE ==================
// C[M,N] = A[M,K]*Bm[K,N]; one accumulator per element, strict ascending-k
// fma.rn.f32x2 chain (bit-identical logits). BM=128, BN=64, BK=32, 128 threads,
// thread tile 8m x 8n. Permuted dup-A smem: u64 index j = q*32 + ty*2 + h <->
// row m = ty*8 + q*2 + h -> warp A-reads are 64B-contiguous (1 wavefront each).
// BK=32 halves barriers + kk-pipeline refills vs BK=16 (H grid is 256 CTAs =
// only ~1.7 warps/SMSP, so boundary drains are unhidden).  Smem 80 KB (dynamic).
static constexpr int H_BM = 128, H_BN = 64, H_BK = 32;
static constexpr int H_SMEM = 2 * H_BK * H_BM * 8 + 2 * H_BK * H_BN * 4;  // 81920

template<int SCORE>
__global__ __launch_bounds__(128, 2)
void k_gemm_h(const float* __restrict__ A, const float* __restrict__ Bm,
              const float* __restrict__ bias, const float* __restrict__ U,
              float* __restrict__ Out, float* __restrict__ Score,
              int K, int N)
{
    constexpr int BM = H_BM, BN = H_BN, BK = H_BK;
    extern __shared__ __align__(16) char dsm[];
    u64*   Asp = (u64*)dsm;                        // [2][BK][BM]
    float* Bsp = (float*)(dsm + 2 * BK * BM * 8);  // [2][BK][BN]

    const int tid = threadIdx.x;
    const int tx = tid & 7, ty = tid >> 3;
    const int m0 = blockIdx.y * BM, n0 = blockIdx.x * BN;

    // A loader: column tid holds row arow (permute inverse), 32 consecutive k.
    const int arow = ((tid >> 1) & 15) * 8 + (tid >> 5) * 2 + (tid & 1);
    const float* Aload = A + (size_t)(m0 + arow) * K;
    // B loader: 32 rows x 64 floats; 16 consecutive floats per thread.
    const int brow = tid >> 2, bcol = (tid & 3) * 16;
    const float* Bload = Bm + (size_t)brow * N + n0 + bcol;

    // acc[m 0..7][j 0..3]: u64 = fp32 pair, cols ((j>>1)*32 + tx*4 + 2*(j&1), +1)
    u64 acc[8][4];
#pragma unroll
    for (int m = 0; m < 8; ++m)
#pragma unroll
        for (int j = 0; j < 4; ++j) acc[m][j] = 0ull;

    float4 pa[8], pb[4];

    // ---- prologue: tile 0 ----
#pragma unroll
    for (int q = 0; q < 8; ++q) pa[q] = *(const float4*)(Aload + q * 4);
#pragma unroll
    for (int q = 0; q < 4; ++q) pb[q] = *(const float4*)(Bload + q * 4);
#pragma unroll
    for (int c = 0; c < 32; ++c)
        Asp[c * BM + tid] = dup32(((const float*)&pa[0])[c]);
#pragma unroll
    for (int q = 0; q < 4; ++q)
        *(float4*)&Bsp[brow * BN + bcol + q * 4] = pb[q];
    __syncthreads();

    const int nk = K / BK;
    int buf = 0;
    for (int t = 0; t < nk; ++t) {
        if (t + 1 < nk) {
            const float* Ap = Aload + (t + 1) * BK;
            const float* Bp = Bload + (size_t)(t + 1) * BK * N;
#pragma unroll
            for (int q = 0; q < 8; ++q) pa[q] = *(const float4*)(Ap + q * 4);
#pragma unroll
            for (int q = 0; q < 4; ++q) pb[q] = *(const float4*)(Bp + q * 4);
        }
        // strict ascending-k serial accumulation, operands prefetched 1 kk ahead
        const u64*   Ab = Asp + buf * (BK * BM);
        const float* Bb = Bsp + buf * (BK * BN);
        u64 apr[2][8], bpr[2][4];
#pragma unroll
        for (int q = 0; q < 4; ++q) {
            ulonglong2 a2 = *(const ulonglong2*)&Ab[q * 32 + ty * 2];
            apr[0][q * 2] = a2.x; apr[0][q * 2 + 1] = a2.y;
        }
#pragma unroll
        for (int q = 0; q < 2; ++q) {
            ulonglong2 b2 = *(const ulonglong2*)&Bb[q * 32 + tx * 4];
            bpr[0][q * 2] = b2.x; bpr[0][q * 2 + 1] = b2.y;
        }
#pragma unroll
        for (int kk = 0; kk < BK; ++kk) {
            const int cs = kk & 1;
            if (kk + 1 < BK) {
#pragma unroll
                for (int q = 0; q < 4; ++q) {
                    ulonglong2 a2 = *(const ulonglong2*)&Ab[(kk + 1) * BM + q * 32 + ty * 2];
                    apr[cs ^ 1][q * 2] = a2.x; apr[cs ^ 1][q * 2 + 1] = a2.y;
                }
#pragma unroll
                for (int q = 0; q < 2; ++q) {
                    ulonglong2 b2 = *(const ulonglong2*)&Bb[(kk + 1) * BN + q * 32 + tx * 4];
                    bpr[cs ^ 1][q * 2] = b2.x; bpr[cs ^ 1][q * 2 + 1] = b2.y;
                }
            }
#pragma unroll
            for (int m = 0; m < 8; ++m)
#pragma unroll
                for (int j = 0; j < 4; ++j)
                    ffma2(acc[m][j], apr[cs][m], bpr[cs][j]);
        }
        if (t + 1 < nk) {
            const int nb = buf ^ 1;
            u64*   Ad = Asp + nb * (BK * BM);
            float* Bd = Bsp + nb * (BK * BN);
#pragma unroll
            for (int c = 0; c < 32; ++c)
                Ad[c * BM + tid] = dup32(((const float*)&pa[0])[c]);
#pragma unroll
            for (int q = 0; q < 4; ++q)
                *(float4*)&Bd[brow * BN + bcol + q * 4] = pb[q];
        }
        __syncthreads();
        buf ^= 1;
    }

    // ---- epilogue: bias + sigmoid + Bernoulli + optional score partial ----
    float biasv[8];
#pragma unroll
    for (int q = 0; q < 2; ++q)
        *(float4*)&biasv[q * 4] = *(const float4*)(bias + n0 + q * 32 + tx * 4);
#pragma unroll
    for (int m = 0; m < 8; ++m) {
        int gm = m0 + ty * 8 + m;
        float sp = 0.f;
#pragma unroll
        for (int q = 0; q < 2; ++q) {
            int gn = n0 + q * 32 + tx * 4;
            float4 u4 = *(const float4*)(U + (size_t)gm * N + gn);
            float2 e0 = *(float2*)&acc[m][q * 2];
            float2 e1 = *(float2*)&acc[m][q * 2 + 1];
            float l[4] = { e0.x + biasv[q*4],   e0.y + biasv[q*4+1],
                           e1.x + biasv[q*4+2], e1.y + biasv[q*4+3] };
            float s[4];
#pragma unroll
            for (int j = 0; j < 4; ++j) {
                float pr = 1.0f / (1.0f + expf(-l[j]));
                s[j] = (pr > ((const float*)&u4)[j]) ? 1.0f : 0.0f;
            }
            *(float4*)(Out + (size_t)gm * N + gn) = make_float4(s[0], s[1], s[2], s[3]);
            if (SCORE) sp += s[0]*l[0] + s[1]*l[1] + s[2]*l[2] + s[3]*l[3];
        }
        if (SCORE) {
            sp += __shfl_xor_sync(0xffffffffu, sp, 1);
            sp += __shfl_xor_sync(0xffffffffu, sp, 2);
            sp += __shfl_xor_sync(0xffffffffu, sp, 4);
            if (tx == 0) Score[(size_t)gm * gridDim.x + blockIdx.x] = sp;
        }
    }
}

// ======================= V-output GEMM: r11 body verbatim (BK=16) ==================
template<int SCORE>
__global__ __launch_bounds__(128, 3)
void k_gemm_v(const float* __restrict__ A, const float* __restrict__ Bm,
              const float* __restrict__ bias, const float* __restrict__ U,
              float* __restrict__ Out, float* __restrict__ Score,
              int K, int N)
{
    constexpr int BM = 128, BN = 64, BK = 16;
    __shared__ __align__(16) u64   As[2][BK][BM];
    __shared__ __align__(16) float Bs[2][BK][BN];

    const int tid = threadIdx.x;
    const int tx = tid & 7, ty = tid >> 3;
    const int m0 = blockIdx.y * BM, n0 = blockIdx.x * BN;

    const int arow = ((tid >> 1) & 15) * 8 + (tid >> 5) * 2 + (tid & 1);
    const float* Aload = A + (size_t)(m0 + arow) * K;
    const int brow = tid >> 3, bcol = (tid & 7) * 8;
    const float* Bload = Bm + (size_t)brow * N + n0 + bcol;

    u64 acc[8][4];
#pragma unroll
    for (int m = 0; m < 8; ++m)
#pragma unroll
        for (int j = 0; j < 4; ++j) acc[m][j] = 0ull;

    float4 pa[4], pb[2];

#pragma unroll
    for (int q = 0; q < 4; ++q) pa[q] = *(const float4*)(Aload + q * 4);
#pragma unroll
    for (int q = 0; q < 2; ++q) pb[q] = *(const float4*)(Bload + q * 4);
#pragma unroll
    for (int c = 0; c < 16; ++c)
        As[0][c][tid] = dup32(((const float*)&pa[0])[c]);
#pragma unroll
    for (int q = 0; q < 2; ++q)
        *(float4*)&Bs[0][brow][bcol + q * 4] = pb[q];
    __syncthreads();

    const int nk = K / BK;
    int buf = 0;
    for (int t = 0; t < nk; ++t) {
        if (t + 1 < nk) {
            const float* Ap = Aload + (t + 1) * BK;
            const float* Bp = Bload + (size_t)(t + 1) * BK * N;
#pragma unroll
            for (int q = 0; q < 4; ++q) pa[q] = *(const float4*)(Ap + q * 4);
#pragma unroll
            for (int q = 0; q < 2; ++q) pb[q] = *(const float4*)(Bp + q * 4);
        }
#pragma unroll
        for (int kk = 0; kk < BK; ++kk) {
            u64 ap[8];
#pragma unroll
            for (int q = 0; q < 4; ++q) {
                ulonglong2 a2 = *(const ulonglong2*)&As[buf][kk][q * 32 + ty * 2];
                ap[q * 2] = a2.x; ap[q * 2 + 1] = a2.y;
            }
            u64 bp[4];
#pragma unroll
            for (int q = 0; q < 2; ++q) {
                ulonglong2 b2 = *(const ulonglong2*)&Bs[buf][kk][q * 32 + tx * 4];
                bp[q * 2] = b2.x; bp[q * 2 + 1] = b2.y;
            }
#pragma unroll
            for (int m = 0; m < 8; ++m)
#pragma unroll
                for (int j = 0; j < 4; ++j)
                    ffma2(acc[m][j], ap[m], bp[j]);
        }
        if (t + 1 < nk) {
            int nb = buf ^ 1;
#pragma unroll
            for (int c = 0; c < 16; ++c)
                As[nb][c][tid] = dup32(((const float*)&pa[0])[c]);
#pragma unroll
            for (int q = 0; q < 2; ++q)
                *(float4*)&Bs[nb][brow][bcol + q * 4] = pb[q];
        }
        __syncthreads();
        buf ^= 1;
    }

    float biasv[8];
#pragma unroll
    for (int q = 0; q < 2; ++q)
        *(float4*)&biasv[q * 4] = *(const float4*)(bias + n0 + q * 32 + tx * 4);
#pragma unroll
    for (int m = 0; m < 8; ++m) {
        int gm = m0 + ty * 8 + m;
        float sp = 0.f;
#pragma unroll
        for (int q = 0; q < 2; ++q) {
            int gn = n0 + q * 32 + tx * 4;
            float4 u4 = *(const float4*)(U + (size_t)gm * N + gn);
            float2 e0 = *(float2*)&acc[m][q * 2];
            float2 e1 = *(float2*)&acc[m][q * 2 + 1];
            float l[4] = { e0.x + biasv[q*4],   e0.y + biasv[q*4+1],
                           e1.x + biasv[q*4+2], e1.y + biasv[q*4+3] };
            float s[4];
#pragma unroll
            for (int j = 0; j < 4; ++j) {
                float pr = 1.0f / (1.0f + expf(-l[j]));
                s[j] = (pr > ((const float*)&u4)[j]) ? 1.0f : 0.0f;
            }
            *(float4*)(Out + (size_t)gm * N + gn) = make_float4(s[0], s[1], s[2], s[3]);
            if (SCORE) sp += s[0]*l[0] + s[1]*l[1] + s[2]*l[2] + s[3]*l[3];
        }
        if (SCORE) {
            sp += __shfl_xor_sync(0xffffffffu, sp, 1);
            sp += __shfl_xor_sync(0xffffffffu, sp, 2);
            sp += __shfl_xor_sync(0xffffffffu, sp, 4);
            if (tx == 0) Score[(size_t)gm * gridDim.x + blockIdx.x] = sp;
        }
    }
}

// ---------------- finalize: out[b] = (v.b_v + pos) - (neg + h2.b_h) ----------------
__global__ void k_finalize(const float* __restrict__ visible, const float* __restrict__ b_v,
                           const float* __restrict__ b_h, float* __restrict__ out)
{
    int b = blockIdx.x, tid = threadIdx.x;
    float acc = 0.f;
    const float* vr = visible + (size_t)b * RBM_V;
    for (int i = tid; i < RBM_V; i += 256) acc += vr[i] * b_v[i];
    const float* hr = g_h + (size_t)b * RBM_H;            // g_h holds h2 here
    for (int i = tid; i < RBM_H; i += 256) acc -= hr[i] * b_h[i];
    if (tid < 16) acc += g_pos[b * 16 + tid];             // 16 n-tiles (N=1024, BN=64)
    if (tid < 64) acc -= g_neg[b * 64 + tid];             // 64 n-tiles (N=4096, BN=64)
    __shared__ float red[256];
    red[tid] = acc;
    __syncthreads();
    for (int o = 128; o; o >>= 1) { if (tid < o) red[tid] += red[tid + o]; __syncthreads(); }
    if (tid == 0) out[b] = red[0];
}

// ---------------- launch ----------------
extern "C" void kernel_launch(void* const* d_in, const int* in_sizes, int n_in,
                              void* d_out, int out_size)
{
    const float* visible = (const float*)d_in[0];
    const float* b_v     = (const float*)d_in[1];
    const float* b_h     = (const float*)d_in[2];
    const float* W       = (const float*)d_in[3];
    const float* u_h0    = (const float*)d_in[4];
    const float* u_v     = (const float*)d_in[5];
    const float* u_h     = (const float*)d_in[6];
    float* out = (float*)d_out;

    float *WT, *hb, *vb, *pos, *neg;
    cudaGetSymbolAddress((void**)&WT,  g_WT);
    cudaGetSymbolAddress((void**)&hb,  g_h);
    cudaGetSymbolAddress((void**)&vb,  g_v);
    cudaGetSymbolAddress((void**)&pos, g_pos);
    cudaGetSymbolAddress((void**)&neg, g_neg);

    static int smem_set = 0;
    if (!smem_set) {
        cudaFuncSetAttribute(k_gemm_h<0>, cudaFuncAttributeMaxDynamicSharedMemorySize, H_SMEM);
        cudaFuncSetAttribute(k_gemm_h<1>, cudaFuncAttributeMaxDynamicSharedMemorySize, H_SMEM);
        smem_set = 1;
    }

    k_transpose<<<dim3(RBM_H / 32, RBM_V / 32), dim3(32, 8)>>>(W, WT);

    dim3 gH(RBM_H / 64, RBM_B / 128);   // (16, 16) = 256 CTAs
    dim3 gV(RBM_V / 64, RBM_B / 128);   // (64, 16) = 1024 CTAs

    const size_t BV = (size_t)RBM_B * RBM_V;
    const size_t BH = (size_t)RBM_B * RBM_H;

    // positive phase: h0 | data, fused pos-score
    k_gemm_h<1><<<gH, 128, H_SMEM>>>(visible, W,  b_h, u_h0,        hb, pos,    RBM_V, RBM_H);
    // Gibbs chain: v,h,v,h,v
    k_gemm_v<0><<<gV, 128>>>(hb,      WT, b_v, u_v + 0*BV,  vb, nullptr, RBM_H, RBM_V);
    k_gemm_h<0><<<gH, 128, H_SMEM>>>(vb,      W,  b_h, u_h + 0*BH,  hb, nullptr, RBM_V, RBM_H);
    k_gemm_v<0><<<gV, 128>>>(hb,      WT, b_v, u_v + 1*BV,  vb, nullptr, RBM_H, RBM_V);
    k_gemm_h<0><<<gH, 128, H_SMEM>>>(vb,      W,  b_h, u_h + 1*BH,  hb, nullptr, RBM_V, RBM_H);
    // last v-step: fused neg-score
    k_gemm_v<2><<<gV, 128>>>(hb,      WT, b_v, u_v + 2*BV,  vb, neg,     RBM_H, RBM_V);

    k_finalize<<<RBM_B, 256>>>(visible, b_v, b_h, out);
}

// round 15
// speedup vs baseline: 1.0886x; 1.0423x over previous
#include <cuda_runtime.h>
#include <math.h>

#define RBM_B 2048
#define RBM_V 4096
#define RBM_H 1024

// Scratch (device globals: allocation-free rule)
static __device__ float g_WT[(size_t)RBM_H * RBM_V];   // 16 MB  W transposed [H,V]
static __device__ float g_h [(size_t)RBM_B * RBM_H];   //  8 MB  current h
static __device__ float g_v [(size_t)RBM_B * RBM_V];   // 32 MB  current v
static __device__ float g_pos[RBM_B * 16];             // pos partials (16 n-tiles, BN=64)
static __device__ float g_neg[RBM_B * 64];             // neg partials (64 n-tiles, BN=64)

typedef unsigned long long u64;

// packed f32x2 FMA (full-rate fp32 on sm_103a; per-lane rounding == scalar FFMA)
__device__ __forceinline__ void ffma2(u64& d, u64 a, u64 b) {
    asm("fma.rn.f32x2 %0, %1, %2, %0;" : "+l"(d) : "l"(a), "l"(b));
}
__device__ __forceinline__ u64 dup32(float v) {
    unsigned u = __float_as_uint(v);
    return (u64)u | ((u64)u << 32);
}

// ---------------- transpose W[V,H] -> WT[H,V] ----------------
__global__ void k_transpose(const float* __restrict__ W, float* __restrict__ WT) {
    __shared__ float t[32][33];
    int h0 = blockIdx.x * 32, v0 = blockIdx.y * 32;
#pragma unroll
    for (int i = 0; i < 4; ++i)
        t[threadIdx.y + 8*i][threadIdx.x] =
            W[(size_t)(v0 + threadIdx.y + 8*i) * RBM_H + h0 + threadIdx.x];
    __syncthreads();
#pragma unroll
    for (int i = 0; i < 4; ++i)
        WT[(size_t)(h0 + threadIdx.y + 8*i) * RBM_V + v0 + threadIdx.x] =
            t[threadIdx.x][threadIdx.y + 8*i];
}

// ---------------- fused GEMM + bias + sigmoid-Bernoulli sample (+score) ----------------
// C[M,N] = A[M,K] * Bm[K,N]; A binary {0,1}.
// CRITICAL: one accumulator per output element, strict ascending-k fma.rn.f32x2 chain
// (bit-identical logits to all passing rounds). SIMD pairs along n.
// BM=128, BN=64, BK=16, 128 threads, thread tile 8m x 8n.
// Permuted As: u64 index j = q*32 + ty*2 + h <-> row m = ty*8 + q*2 + h, so each
// warp's A-read (ulonglong2 at q*32 + ty*2) is 64B-contiguous: 1 wavefront.
// PIPE=1 (H-out, grid 256): next-kk operand preload, __launch_bounds__(128,2).
// PIPE=0 (V-out, grid 1024, 3 CTA/SM): plain body, bounds(128,3).
// ANTI-RESONANCE: co-resident CTAs of the same kernel run identical instruction
// streams and phase-lock on the per-tile __syncthreads, emptying the SM during
// every barrier drain. A one-time entry stagger (~half a tile period) anti-phases
// same-SM CTA pairs; the pipeline is self-timed afterwards. No effect on values.
template<int SCORE, int PIPE>
__global__ __launch_bounds__(128, (PIPE ? 2 : 3))
void k_gemm_sample(const float* __restrict__ A, const float* __restrict__ Bm,
                   const float* __restrict__ bias, const float* __restrict__ U,
                   float* __restrict__ Out, float* __restrict__ Score,
                   int K, int N)
{
    constexpr int BM = 128, BN = 64, BK = 16;
    __shared__ __align__(16) u64   As[2][BK][BM];      // dup-A, permuted: 32 KB
    __shared__ __align__(16) float Bs[2][BK][BN];      // plain B: 8 KB

    // anti-resonance stagger (same-SM pairs are bid & bid+148; with gridDim.x=16
    // the parity of bx+by flips across +148 for 75% of pairs; mod-3 spreads the
    // 3-resident V case)
    if (PIPE) {
        if ((blockIdx.x + blockIdx.y) & 1) __nanosleep(500);
    } else {
        unsigned r = (blockIdx.x + blockIdx.y) % 3;
        if (r) __nanosleep(r * 330);
    }

    const int tid = threadIdx.x;
    const int tx = tid & 7, ty = tid >> 3;
    const int m0 = blockIdx.y * BM, n0 = blockIdx.x * BN;

    // A loader: thread stores column tid; the row it loads is the permute-inverse.
    const int arow = ((tid >> 1) & 15) * 8 + (tid >> 5) * 2 + (tid & 1);
    const float* Aload = A + (size_t)(m0 + arow) * K;
    // B loader: 16 rows x 64 floats, 8 per thread.
    const int brow = tid >> 3, bcol = (tid & 7) * 8;
    const float* Bload = Bm + (size_t)brow * N + n0 + bcol;

    // acc[m 0..7][j 0..3]: u64 = fp32 pair, columns ((j>>1)*32 + tx*4 + 2*(j&1), +1)
    u64 acc[8][4];
#pragma unroll
    for (int m = 0; m < 8; ++m)
#pragma unroll
        for (int j = 0; j < 4; ++j) acc[m][j] = 0ull;

    float4 pa[4], pb[2];

    // ---- prologue: tile 0 ----
#pragma unroll
    for (int q = 0; q < 4; ++q) pa[q] = *(const float4*)(Aload + q * 4);
#pragma unroll
    for (int q = 0; q < 2; ++q) pb[q] = *(const float4*)(Bload + q * 4);
#pragma unroll
    for (int c = 0; c < 16; ++c)
        As[0][c][tid] = dup32(((const float*)&pa[0])[c]);
#pragma unroll
    for (int q = 0; q < 2; ++q)
        *(float4*)&Bs[0][brow][bcol + q * 4] = pb[q];
    __syncthreads();

    const int nk = K / BK;
    int buf = 0;
    for (int t = 0; t < nk; ++t) {
        if (t + 1 < nk) {
            const float* Ap = Aload + (t + 1) * BK;
            const float* Bp = Bload + (size_t)(t + 1) * BK * N;
#pragma unroll
            for (int q = 0; q < 4; ++q) pa[q] = *(const float4*)(Ap + q * 4);
#pragma unroll
            for (int q = 0; q < 2; ++q) pb[q] = *(const float4*)(Bp + q * 4);
        }
        // strict ascending-k serial accumulation (32 independent FFMA2 chains)
        if (PIPE) {
            u64 apr[2][8], bpr[2][4];
#pragma unroll
            for (int q = 0; q < 4; ++q) {
                ulonglong2 a2 = *(const ulonglong2*)&As[buf][0][q * 32 + ty * 2];
                apr[0][q * 2] = a2.x; apr[0][q * 2 + 1] = a2.y;
            }
#pragma unroll
            for (int q = 0; q < 2; ++q) {
                ulonglong2 b2 = *(const ulonglong2*)&Bs[buf][0][q * 32 + tx * 4];
                bpr[0][q * 2] = b2.x; bpr[0][q * 2 + 1] = b2.y;
            }
#pragma unroll
            for (int kk = 0; kk < BK; ++kk) {
                const int cs = kk & 1;
                if (kk + 1 < BK) {
#pragma unroll
                    for (int q = 0; q < 4; ++q) {
                        ulonglong2 a2 = *(const ulonglong2*)&As[buf][kk + 1][q * 32 + ty * 2];
                        apr[cs ^ 1][q * 2] = a2.x; apr[cs ^ 1][q * 2 + 1] = a2.y;
                    }
#pragma unroll
                    for (int q = 0; q < 2; ++q) {
                        ulonglong2 b2 = *(const ulonglong2*)&Bs[buf][kk + 1][q * 32 + tx * 4];
                        bpr[cs ^ 1][q * 2] = b2.x; bpr[cs ^ 1][q * 2 + 1] = b2.y;
                    }
                }
#pragma unroll
                for (int m = 0; m < 8; ++m)
#pragma unroll
                    for (int j = 0; j < 4; ++j)
                        ffma2(acc[m][j], apr[cs][m], bpr[cs][j]);
            }
        } else {
#pragma unroll
            for (int kk = 0; kk < BK; ++kk) {
                u64 ap[8];
#pragma unroll
                for (int q = 0; q < 4; ++q) {
                    ulonglong2 a2 = *(const ulonglong2*)&As[buf][kk][q * 32 + ty * 2];
                    ap[q * 2] = a2.x; ap[q * 2 + 1] = a2.y;
                }
                u64 bp[4];
#pragma unroll
                for (int q = 0; q < 2; ++q) {
                    ulonglong2 b2 = *(const ulonglong2*)&Bs[buf][kk][q * 32 + tx * 4];
                    bp[q * 2] = b2.x; bp[q * 2 + 1] = b2.y;
                }
#pragma unroll
                for (int m = 0; m < 8; ++m)
#pragma unroll
                    for (int j = 0; j < 4; ++j)
                        ffma2(acc[m][j], ap[m], bp[j]);
            }
        }
        if (t + 1 < nk) {
            int nb = buf ^ 1;
#pragma unroll
            for (int c = 0; c < 16; ++c)
                As[nb][c][tid] = dup32(((const float*)&pa[0])[c]);
#pragma unroll
            for (int q = 0; q < 2; ++q)
                *(float4*)&Bs[nb][brow][bcol + q * 4] = pb[q];
        }
        __syncthreads();
        buf ^= 1;
    }

    // ---- epilogue: bias + sigmoid + Bernoulli + optional per-row score partial ----
    float biasv[8];
#pragma unroll
    for (int q = 0; q < 2; ++q)
        *(float4*)&biasv[q * 4] = *(const float4*)(bias + n0 + q * 32 + tx * 4);
#pragma unroll
    for (int m = 0; m < 8; ++m) {
        int gm = m0 + ty * 8 + m;
        float sp = 0.f;
#pragma unroll
        for (int q = 0; q < 2; ++q) {
            int gn = n0 + q * 32 + tx * 4;
            float4 u4 = *(const float4*)(U + (size_t)gm * N + gn);
            float2 e0 = *(float2*)&acc[m][q * 2];
            float2 e1 = *(float2*)&acc[m][q * 2 + 1];
            float l[4] = { e0.x + biasv[q*4],   e0.y + biasv[q*4+1],
                           e1.x + biasv[q*4+2], e1.y + biasv[q*4+3] };
            float s[4];
#pragma unroll
            for (int j = 0; j < 4; ++j) {
                float pr = 1.0f / (1.0f + expf(-l[j]));   // libdevice expf + IEEE div
                s[j] = (pr > ((const float*)&u4)[j]) ? 1.0f : 0.0f;
            }
            *(float4*)(Out + (size_t)gm * N + gn) = make_float4(s[0], s[1], s[2], s[3]);
            if (SCORE) sp += s[0]*l[0] + s[1]*l[1] + s[2]*l[2] + s[3]*l[3];
        }
        if (SCORE) {
            sp += __shfl_xor_sync(0xffffffffu, sp, 1);
            sp += __shfl_xor_sync(0xffffffffu, sp, 2);
            sp += __shfl_xor_sync(0xffffffffu, sp, 4);
            if (tx == 0) Score[(size_t)gm * gridDim.x + blockIdx.x] = sp;
        }
    }
}

// ---------------- finalize: out[b] = (v.b_v + pos) - (neg + h2.b_h) ----------------
__global__ void k_finalize(const float* __restrict__ visible, const float* __restrict__ b_v,
                           const float* __restrict__ b_h, float* __restrict__ out)
{
    int b = blockIdx.x, tid = threadIdx.x;
    float acc = 0.f;
    const float* vr = visible + (size_t)b * RBM_V;
    for (int i = tid; i < RBM_V; i += 256) acc += vr[i] * b_v[i];
    const float* hr = g_h + (size_t)b * RBM_H;            // g_h holds h2 here
    for (int i = tid; i < RBM_H; i += 256) acc -= hr[i] * b_h[i];
    if (tid < 16) acc += g_pos[b * 16 + tid];             // 16 n-tiles (N=1024, BN=64)
    if (tid < 64) acc -= g_neg[b * 64 + tid];             // 64 n-tiles (N=4096, BN=64)
    __shared__ float red[256];
    red[tid] = acc;
    __syncthreads();
    for (int o = 128; o; o >>= 1) { if (tid < o) red[tid] += red[tid + o]; __syncthreads(); }
    if (tid == 0) out[b] = red[0];
}

// ---------------- launch ----------------
extern "C" void kernel_launch(void* const* d_in, const int* in_sizes, int n_in,
                              void* d_out, int out_size)
{
    const float* visible = (const float*)d_in[0];
    const float* b_v     = (const float*)d_in[1];
    const float* b_h     = (const float*)d_in[2];
    const float* W       = (const float*)d_in[3];
    const float* u_h0    = (const float*)d_in[4];
    const float* u_v     = (const float*)d_in[5];
    const float* u_h     = (const float*)d_in[6];
    float* out = (float*)d_out;

    float *WT, *hb, *vb, *pos, *neg;
    cudaGetSymbolAddress((void**)&WT,  g_WT);
    cudaGetSymbolAddress((void**)&hb,  g_h);
    cudaGetSymbolAddress((void**)&vb,  g_v);
    cudaGetSymbolAddress((void**)&pos, g_pos);
    cudaGetSymbolAddress((void**)&neg, g_neg);

    k_transpose<<<dim3(RBM_H / 32, RBM_V / 32), dim3(32, 8)>>>(W, WT);

    dim3 blk(128);
    dim3 gH(RBM_H / 64, RBM_B / 128);   // (16, 16) = 256 CTAs  (PIPE=1)
    dim3 gV(RBM_V / 64, RBM_B / 128);   // (64, 16) = 1024 CTAs (PIPE=0)

    const size_t BV = (size_t)RBM_B * RBM_V;
    const size_t BH = (size_t)RBM_B * RBM_H;

    // positive phase: h0 | data, fused pos-score
    k_gemm_sample<1,1><<<gH, blk>>>(visible, W,  b_h, u_h0,        hb, pos,    RBM_V, RBM_H);
    // Gibbs chain: v,h,v,h,v
    k_gemm_sample<0,0><<<gV, blk>>>(hb,      WT, b_v, u_v + 0*BV,  vb, nullptr, RBM_H, RBM_V);
    k_gemm_sample<0,1><<<gH, blk>>>(vb,      W,  b_h, u_h + 0*BH,  hb, nullptr, RBM_V, RBM_H);
    k_gemm_sample<0,0><<<gV, blk>>>(hb,      WT, b_v, u_v + 1*BV,  vb, nullptr, RBM_H, RBM_V);
    k_gemm_sample<0,1><<<gH, blk>>>(vb,      W,  b_h, u_h + 1*BH,  hb, nullptr, RBM_V, RBM_H);
    // last v-step: fused neg-score
    k_gemm_sample<2,0><<<gV, blk>>>(hb,      WT, b_v, u_v + 2*BV,  vb, neg,     RBM_H, RBM_V);

    k_finalize<<<RBM_B, 256>>>(visible, b_v, b_h, out);
}

// round 16
// speedup vs baseline: 1.0924x; 1.0035x over previous
#include <cuda_runtime.h>
#include <math.h>

#define RBM_B 2048
#define RBM_V 4096
#define RBM_H 1024

// Scratch (device globals: allocation-free rule)
static __device__ float g_WT[(size_t)RBM_H * RBM_V];   // 16 MB  W transposed [H,V]
static __device__ float g_h [(size_t)RBM_B * RBM_H];   //  8 MB  current h
static __device__ float g_v [(size_t)RBM_B * RBM_V];   // 32 MB  current v
static __device__ float g_pos[RBM_B * 16];             // pos partials (16 n-tiles, BN=64)
static __device__ float g_neg[RBM_B * 64];             // neg partials (64 n-tiles, BN=64)

typedef unsigned long long u64;

// packed f32x2 FMA (full-rate fp32 on sm_103a; per-lane rounding == scalar FFMA)
__device__ __forceinline__ void ffma2(u64& d, u64 a, u64 b) {
    asm("fma.rn.f32x2 %0, %1, %2, %0;" : "+l"(d) : "l"(a), "l"(b));
}
__device__ __forceinline__ u64 dup32(float v) {
    unsigned u = __float_as_uint(v);
    return (u64)u | ((u64)u << 32);
}

// ---------------- transpose W[V,H] -> WT[H,V] ----------------
__global__ void k_transpose(const float* __restrict__ W, float* __restrict__ WT) {
    __shared__ float t[32][33];
    int h0 = blockIdx.x * 32, v0 = blockIdx.y * 32;
#pragma unroll
    for (int i = 0; i < 4; ++i)
        t[threadIdx.y + 8*i][threadIdx.x] =
            W[(size_t)(v0 + threadIdx.y + 8*i) * RBM_H + h0 + threadIdx.x];
    __syncthreads();
#pragma unroll
    for (int i = 0; i < 4; ++i)
        WT[(size_t)(h0 + threadIdx.y + 8*i) * RBM_V + v0 + threadIdx.x] =
            t[threadIdx.x][threadIdx.y + 8*i];
}

// ---------------- fused GEMM + bias + sigmoid-Bernoulli sample (+score) ----------------
// C[M,N] = A[M,K] * Bm[K,N]; A binary {0,1}.
// CRITICAL: one accumulator per output element, strict ascending-k fma.rn.f32x2 chain
// (bit-identical logits to all passing rounds). SIMD pairs along n.
// BM=128, BN=64, BK=16, 128 threads, thread tile 8m x 8n.
// Permuted As: u64 index j = q*32 + ty*2 + h <-> row m = ty*8 + q*2 + h, so each
// warp's A-read (ulonglong2 at q*32 + ty*2) is 64B-contiguous: 1 wavefront.
// PIPE=1 (H-out, grid 256): next-kk operand preload, __launch_bounds__(128,2).
// PIPE=0 (V-out, grid 1024, 3 CTA/SM): plain body, bounds(128,3).
// SCORE==2: last Gibbs step -- samples are consumed entirely by the in-kernel
// neg-score partial; the 32 MB Out store is dead and skipped.
template<int SCORE, int PIPE>
__global__ __launch_bounds__(128, (PIPE ? 2 : 3))
void k_gemm_sample(const float* __restrict__ A, const float* __restrict__ Bm,
                   const float* __restrict__ bias, const float* __restrict__ U,
                   float* __restrict__ Out, float* __restrict__ Score,
                   int K, int N)
{
    constexpr int BM = 128, BN = 64, BK = 16;
    __shared__ __align__(16) u64   As[2][BK][BM];      // dup-A, permuted: 32 KB
    __shared__ __align__(16) float Bs[2][BK][BN];      // plain B: 8 KB

    const int tid = threadIdx.x;
    const int tx = tid & 7, ty = tid >> 3;
    const int m0 = blockIdx.y * BM, n0 = blockIdx.x * BN;

    // A loader: thread stores column tid; the row it loads is the permute-inverse.
    const int arow = ((tid >> 1) & 15) * 8 + (tid >> 5) * 2 + (tid & 1);
    const float* Aload = A + (size_t)(m0 + arow) * K;
    // B loader: 16 rows x 64 floats, 8 per thread.
    const int brow = tid >> 3, bcol = (tid & 7) * 8;
    const float* Bload = Bm + (size_t)brow * N + n0 + bcol;

    // acc[m 0..7][j 0..3]: u64 = fp32 pair, columns ((j>>1)*32 + tx*4 + 2*(j&1), +1)
    u64 acc[8][4];
#pragma unroll
    for (int m = 0; m < 8; ++m)
#pragma unroll
        for (int j = 0; j < 4; ++j) acc[m][j] = 0ull;

    float4 pa[4], pb[2];

    // ---- prologue: tile 0 ----
#pragma unroll
    for (int q = 0; q < 4; ++q) pa[q] = *(const float4*)(Aload + q * 4);
#pragma unroll
    for (int q = 0; q < 2; ++q) pb[q] = *(const float4*)(Bload + q * 4);
#pragma unroll
    for (int c = 0; c < 16; ++c)
        As[0][c][tid] = dup32(((const float*)&pa[0])[c]);
#pragma unroll
    for (int q = 0; q < 2; ++q)
        *(float4*)&Bs[0][brow][bcol + q * 4] = pb[q];
    __syncthreads();

    const int nk = K / BK;
    int buf = 0;
    for (int t = 0; t < nk; ++t) {
        if (t + 1 < nk) {
            const float* Ap = Aload + (t + 1) * BK;
            const float* Bp = Bload + (size_t)(t + 1) * BK * N;
#pragma unroll
            for (int q = 0; q < 4; ++q) pa[q] = *(const float4*)(Ap + q * 4);
#pragma unroll
            for (int q = 0; q < 2; ++q) pb[q] = *(const float4*)(Bp + q * 4);
        }
        // strict ascending-k serial accumulation (32 independent FFMA2 chains)
        if (PIPE) {
            u64 apr[2][8], bpr[2][4];
#pragma unroll
            for (int q = 0; q < 4; ++q) {
                ulonglong2 a2 = *(const ulonglong2*)&As[buf][0][q * 32 + ty * 2];
                apr[0][q * 2] = a2.x; apr[0][q * 2 + 1] = a2.y;
            }
#pragma unroll
            for (int q = 0; q < 2; ++q) {
                ulonglong2 b2 = *(const ulonglong2*)&Bs[buf][0][q * 32 + tx * 4];
                bpr[0][q * 2] = b2.x; bpr[0][q * 2 + 1] = b2.y;
            }
#pragma unroll
            for (int kk = 0; kk < BK; ++kk) {
                const int cs = kk & 1;
                if (kk + 1 < BK) {
#pragma unroll
                    for (int q = 0; q < 4; ++q) {
                        ulonglong2 a2 = *(const ulonglong2*)&As[buf][kk + 1][q * 32 + ty * 2];
                        apr[cs ^ 1][q * 2] = a2.x; apr[cs ^ 1][q * 2 + 1] = a2.y;
                    }
#pragma unroll
                    for (int q = 0; q < 2; ++q) {
                        ulonglong2 b2 = *(const ulonglong2*)&Bs[buf][kk + 1][q * 32 + tx * 4];
                        bpr[cs ^ 1][q * 2] = b2.x; bpr[cs ^ 1][q * 2 + 1] = b2.y;
                    }
                }
#pragma unroll
                for (int m = 0; m < 8; ++m)
#pragma unroll
                    for (int j = 0; j < 4; ++j)
                        ffma2(acc[m][j], apr[cs][m], bpr[cs][j]);
            }
        } else {
#pragma unroll
            for (int kk = 0; kk < BK; ++kk) {
                u64 ap[8];
#pragma unroll
                for (int q = 0; q < 4; ++q) {
                    ulonglong2 a2 = *(const ulonglong2*)&As[buf][kk][q * 32 + ty * 2];
                    ap[q * 2] = a2.x; ap[q * 2 + 1] = a2.y;
                }
                u64 bp[4];
#pragma unroll
                for (int q = 0; q < 2; ++q) {
                    ulonglong2 b2 = *(const ulonglong2*)&Bs[buf][kk][q * 32 + tx * 4];
                    bp[q * 2] = b2.x; bp[q * 2 + 1] = b2.y;
                }
#pragma unroll
                for (int m = 0; m < 8; ++m)
#pragma unroll
                    for (int j = 0; j < 4; ++j)
                        ffma2(acc[m][j], ap[m], bp[j]);
            }
        }
        if (t + 1 < nk) {
            int nb = buf ^ 1;
#pragma unroll
            for (int c = 0; c < 16; ++c)
                As[nb][c][tid] = dup32(((const float*)&pa[0])[c]);
#pragma unroll
            for (int q = 0; q < 2; ++q)
                *(float4*)&Bs[nb][brow][bcol + q * 4] = pb[q];
        }
        __syncthreads();
        buf ^= 1;
    }

    // ---- epilogue: bias + sigmoid + Bernoulli + optional per-row score partial ----
    float biasv[8];
#pragma unroll
    for (int q = 0; q < 2; ++q)
        *(float4*)&biasv[q * 4] = *(const float4*)(bias + n0 + q * 32 + tx * 4);
#pragma unroll
    for (int m = 0; m < 8; ++m) {
        int gm = m0 + ty * 8 + m;
        float sp = 0.f;
#pragma unroll
        for (int q = 0; q < 2; ++q) {
            int gn = n0 + q * 32 + tx * 4;
            float4 u4 = *(const float4*)(U + (size_t)gm * N + gn);
            float2 e0 = *(float2*)&acc[m][q * 2];
            float2 e1 = *(float2*)&acc[m][q * 2 + 1];
            float l[4] = { e0.x + biasv[q*4],   e0.y + biasv[q*4+1],
                           e1.x + biasv[q*4+2], e1.y + biasv[q*4+3] };
            float s[4];
#pragma unroll
            for (int j = 0; j < 4; ++j) {
                float pr = 1.0f / (1.0f + expf(-l[j]));   // libdevice expf + IEEE div
                s[j] = (pr > ((const float*)&u4)[j]) ? 1.0f : 0.0f;
            }
            if (SCORE != 2)   // last Gibbs step: samples die in the score partial
                *(float4*)(Out + (size_t)gm * N + gn) = make_float4(s[0], s[1], s[2], s[3]);
            if (SCORE) sp += s[0]*l[0] + s[1]*l[1] + s[2]*l[2] + s[3]*l[3];
        }
        if (SCORE) {
            sp += __shfl_xor_sync(0xffffffffu, sp, 1);
            sp += __shfl_xor_sync(0xffffffffu, sp, 2);
            sp += __shfl_xor_sync(0xffffffffu, sp, 4);
            if (tx == 0) Score[(size_t)gm * gridDim.x + blockIdx.x] = sp;
        }
    }
}

// ---------------- finalize: out[b] = (v.b_v + pos) - (neg + h2.b_h) ----------------
__global__ void k_finalize(const float* __restrict__ visible, const float* __restrict__ b_v,
                           const float* __restrict__ b_h, float* __restrict__ out)
{
    int b = blockIdx.x, tid = threadIdx.x;
    float acc = 0.f;
    const float* vr = visible + (size_t)b * RBM_V;
    for (int i = tid; i < RBM_V; i += 256) acc += vr[i] * b_v[i];
    const float* hr = g_h + (size_t)b * RBM_H;            // g_h holds h2 here
    for (int i = tid; i < RBM_H; i += 256) acc -= hr[i] * b_h[i];
    if (tid < 16) acc += g_pos[b * 16 + tid];             // 16 n-tiles (N=1024, BN=64)
    if (tid < 64) acc -= g_neg[b * 64 + tid];             // 64 n-tiles (N=4096, BN=64)
    __shared__ float red[256];
    red[tid] = acc;
    __syncthreads();
    for (int o = 128; o; o >>= 1) { if (tid < o) red[tid] += red[tid + o]; __syncthreads(); }
    if (tid == 0) out[b] = red[0];
}

// ---------------- launch ----------------
extern "C" void kernel_launch(void* const* d_in, const int* in_sizes, int n_in,
                              void* d_out, int out_size)
{
    const float* visible = (const float*)d_in[0];
    const float* b_v     = (const float*)d_in[1];
    const float* b_h     = (const float*)d_in[2];
    const float* W       = (const float*)d_in[3];
    const float* u_h0    = (const float*)d_in[4];
    const float* u_v     = (const float*)d_in[5];
    const float* u_h     = (const float*)d_in[6];
    float* out = (float*)d_out;

    float *WT, *hb, *vb, *pos, *neg;
    cudaGetSymbolAddress((void**)&WT,  g_WT);
    cudaGetSymbolAddress((void**)&hb,  g_h);
    cudaGetSymbolAddress((void**)&vb,  g_v);
    cudaGetSymbolAddress((void**)&pos, g_pos);
    cudaGetSymbolAddress((void**)&neg, g_neg);

    dim3 blk(128);
    dim3 gH(RBM_H / 64, RBM_B / 128);   // (16, 16) = 256 CTAs  (PIPE=1)
    dim3 gV(RBM_V / 64, RBM_B / 128);   // (64, 16) = 1024 CTAs (PIPE=0)

    const size_t BV = (size_t)RBM_B * RBM_V;
    const size_t BH = (size_t)RBM_B * RBM_H;

    // Overlap the W-transpose with the first H-GEMM (which reads W, not WT).
    // Fork/join via events so the dependency is captured into the graph.
    // kernel_launch is only invoked twice (correctness + capture), so per-call
    // creation of one stream + two events is cheap; no device memory involved.
    cudaStream_t side;
    cudaEvent_t  evFork, evJoin;
    cudaStreamCreateWithFlags(&side, cudaStreamNonBlocking);
    cudaEventCreateWithFlags(&evFork, cudaEventDisableTiming);
    cudaEventCreateWithFlags(&evJoin, cudaEventDisableTiming);

    cudaEventRecord(evFork, 0);
    cudaStreamWaitEvent(side, evFork, 0);
    k_transpose<<<dim3(RBM_H / 32, RBM_V / 32), dim3(32, 8), 0, side>>>(W, WT);
    cudaEventRecord(evJoin, side);

    // positive phase: h0 | data, fused pos-score (uses W; runs concurrent with transpose)
    k_gemm_sample<1,1><<<gH, blk>>>(visible, W,  b_h, u_h0,        hb, pos,    RBM_V, RBM_H);

    // join: WT must be ready before the first V-GEMM
    cudaStreamWaitEvent(0, evJoin, 0);

    // Gibbs chain: v,h,v,h,v
    k_gemm_sample<0,0><<<gV, blk>>>(hb,      WT, b_v, u_v + 0*BV,  vb, nullptr, RBM_H, RBM_V);
    k_gemm_sample<0,1><<<gH, blk>>>(vb,      W,  b_h, u_h + 0*BH,  hb, nullptr, RBM_V, RBM_H);
    k_gemm_sample<0,0><<<gV, blk>>>(hb,      WT, b_v, u_v + 1*BV,  vb, nullptr, RBM_H, RBM_V);
    k_gemm_sample<0,1><<<gH, blk>>>(vb,      W,  b_h, u_h + 1*BH,  hb, nullptr, RBM_V, RBM_H);
    // last v-step: fused neg-score (Out store elided -- samples consumed in-kernel)
    k_gemm_sample<2,0><<<gV, blk>>>(hb,      WT, b_v, u_v + 2*BV,  vb, neg,     RBM_H, RBM_V);

    k_finalize<<<RBM_B, 256>>>(visible, b_v, b_h, out);
}